// round 6
// baseline (speedup 1.0000x reference)
#include <cuda_runtime.h>
#include <cstdint>
#include <math.h>

#define DIM   768
#define HID   3072
#define HID2  1536
#define NLEV  9
#define SEQ   2048
#define MROWS 4096
#define EPSLN 1e-5f

#define BM 128
#define BN 128
#define BK 32
#define NT 256
#define MAX_TILES 48

#define ASTR 36    /* floats per smem row (32 data + 4 pad): bank-bijective, 16B aligned */
#define ABUF (BM*ASTR)   /* 4608 floats */
#define BBUF (BN*ASTR)   /* 4608 floats */
#define STAGE (ABUF+BBUF)
#define NSTAGE 3
#define SMEM_FLOATS (NSTAGE*STAGE)
#define SMEM_BYTES  (SMEM_FLOATS*4)

#define MID_MAIN_BLKS (6*32)   /* gemm2_main tiles */
#define MID_BLKS (MID_MAIN_BLKS + 12*MAX_TILES)

// ---------------- scratch (no allocations allowed) ----------------
__device__ float g_xnorm[MROWS*DIM];
__device__ float g_h[(size_t)MROWS*HID];
__device__ float g_main[MROWS*DIM];
__device__ float g_hl[MROWS*HID2];
__device__ float g_W1t[DIM*HID];          // transposed+rounded: [HID][DIM]
__device__ float g_W2t[HID*DIM];          // [DIM][HID]
__device__ float g_A1t[NLEV*DIM*HID2];    // per level [HID2][DIM]
__device__ float g_A2t[NLEV*HID2*DIM];    // per level [DIM][HID2]
__device__ float g_mix[SEQ];
__device__ int   g_depth[SEQ];
__device__ int   g_rowperm[MROWS];
__device__ int   g_sched_lvl[MAX_TILES];
__device__ int   g_sched_start[MAX_TILES];
__device__ int   g_sched_rows[MAX_TILES];
__device__ int   g_ntiles;

// ---------------- PTX helpers ----------------
__device__ __forceinline__ uint32_t smem_u32(const void* p) {
    return (uint32_t)__cvta_generic_to_shared(p);
}
__device__ __forceinline__ void cp16(uint32_t dst, const void* src) {
    asm volatile("cp.async.cg.shared.global [%0], [%1], 16;" :: "r"(dst), "l"(src));
}
__device__ __forceinline__ void cp_commit() {
    asm volatile("cp.async.commit_group;" ::: "memory");
}
__device__ __forceinline__ void cp_wait1() {
    asm volatile("cp.async.wait_group 1;" ::: "memory");
}
__device__ __forceinline__ uint32_t f2tf32(float x) {
    uint32_t r;
    asm("cvt.rna.tf32.f32 %0, %1;" : "=r"(r) : "f"(x));
    return r;
}
__device__ __forceinline__ float round_tf32f(float x) {
    return __uint_as_float(f2tf32(x));
}
__device__ __forceinline__ void ldsm_x4(uint32_t& r0, uint32_t& r1, uint32_t& r2, uint32_t& r3,
                                        uint32_t addr) {
    asm volatile("ldmatrix.sync.aligned.m8n8.x4.shared.b16 {%0,%1,%2,%3}, [%4];"
                 : "=r"(r0), "=r"(r1), "=r"(r2), "=r"(r3) : "r"(addr));
}
__device__ __forceinline__ void mma_tf32(float& c0, float& c1, float& c2, float& c3,
                                         uint32_t a0, uint32_t a1, uint32_t a2, uint32_t a3,
                                         uint32_t b0, uint32_t b1) {
    asm volatile(
        "mma.sync.aligned.m16n8k8.row.col.f32.tf32.tf32.f32 "
        "{%0,%1,%2,%3}, {%4,%5,%6,%7}, {%8,%9}, {%0,%1,%2,%3};"
        : "+f"(c0), "+f"(c1), "+f"(c2), "+f"(c3)
        : "r"(a0), "r"(a1), "r"(a2), "r"(a3), "r"(b0), "r"(b1));
}

// ---------------- rounding transpose: src[R][C] -> dst[C][R], tf32-rounded ----------------
__global__ void __launch_bounds__(256) trans_round(const float* __restrict__ src,
                                                   float* __restrict__ dst, int R, int C) {
    __shared__ float ts[32][33];
    size_t zoff = (size_t)blockIdx.z * R * C;
    src += zoff; dst += zoff;
    int tx = threadIdx.x & 31, ty = threadIdx.x >> 5;   // 32 x 8
    int c0 = blockIdx.x * 32, r0 = blockIdx.y * 32;
#pragma unroll
    for (int i = 0; i < 4; ++i)
        ts[ty + i*8][tx] = src[(size_t)(r0 + ty + i*8)*C + c0 + tx];
    __syncthreads();
#pragma unroll
    for (int i = 0; i < 4; ++i)
        dst[(size_t)(c0 + ty + i*8)*R + r0 + tx] = round_tf32f(ts[tx][ty + i*8]);
}

// ---------------- prep: depth clip, counting sort, tile schedule, mix ----------------
__global__ void prep_kernel(const int* __restrict__ levels, const float* __restrict__ lmw) {
    __shared__ int cnt[NLEV];
    __shared__ int cursor[NLEV];
    __shared__ float denom_sh;
    int t = threadIdx.x;
    if (t < NLEV) cnt[t] = 0;
    __syncthreads();
    for (int s = t; s < SEQ; s += NT) {
        int d = levels[s*4];
        d = min(max(d, 0), NLEV-1);
        g_depth[s] = d;
        atomicAdd(&cnt[d], 1);
    }
    __syncthreads();
    if (t == 0) {
        int o = 0, tile = 0;
        float denom = 0.f;
        for (int l = 0; l < NLEV; ++l) {
            cursor[l] = o;
            int rows = 2*cnt[l];
            int nt2 = (rows + BM - 1)/BM;
            for (int i = 0; i < nt2 && tile < MAX_TILES; ++i) {
                g_sched_lvl[tile]   = l;
                g_sched_start[tile] = o + i*BM;
                g_sched_rows[tile]  = min(BM, rows - i*BM);
                ++tile;
            }
            o += rows;
            denom += (float)cnt[l] * expf(lmw[l]);
        }
        for (int i = tile; i < MAX_TILES; ++i) g_sched_rows[i] = 0;
        g_ntiles = tile;
        denom_sh = denom;
    }
    __syncthreads();
    for (int r = t; r < MROWS; r += NT) {
        int s = r & (SEQ-1);
        int d = g_depth[s];
        int pos = atomicAdd(&cursor[d], 1);
        g_rowperm[pos] = r;
    }
    float denom = denom_sh;
    for (int s = t; s < SEQ; s += NT)
        g_mix[s] = expf(lmw[g_depth[s]]) / denom;
}

// ---------------- layernorm (writes tf32-rounded output) ----------------
__global__ void __launch_bounds__(256) ln_kernel(const float* __restrict__ x,
                                                 const float* __restrict__ gamma,
                                                 const float* __restrict__ beta) {
    int row = blockIdx.x;
    int t = threadIdx.x;
    const float* xr = x + (size_t)row*DIM;
    float v0 = xr[t], v1 = xr[t+256], v2 = xr[t+512];
    float s  = v0+v1+v2;
    float sq = v0*v0 + v1*v1 + v2*v2;
    __shared__ float red0[8], red1[8], mv[2];
#pragma unroll
    for (int o = 16; o > 0; o >>= 1) {
        s  += __shfl_xor_sync(0xffffffffu, s,  o);
        sq += __shfl_xor_sync(0xffffffffu, sq, o);
    }
    int wid = t >> 5, lid = t & 31;
    if (lid == 0) { red0[wid] = s; red1[wid] = sq; }
    __syncthreads();
    if (t == 0) {
        float S = 0.f, SQ = 0.f;
#pragma unroll
        for (int i = 0; i < 8; ++i) { S += red0[i]; SQ += red1[i]; }
        float mean = S * (1.0f/DIM);
        float var  = SQ * (1.0f/DIM) - mean*mean;
        mv[0] = mean; mv[1] = rsqrtf(var + EPSLN);
    }
    __syncthreads();
    float mean = mv[0], inv = mv[1];
    float* o = g_xnorm + (size_t)row*DIM;
    o[t]     = round_tf32f((v0-mean)*inv*gamma[t]     + beta[t]);
    o[t+256] = round_tf32f((v1-mean)*inv*gamma[t+256] + beta[t+256]);
    o[t+512] = round_tf32f((v2-mean)*inv*gamma[t+512] + beta[t+512]);
}

// ---------------- chunk loader: A gathered rows, B rows of transposed weights ----------------
__device__ __forceinline__ void load_chunk(const float* __restrict__ A, int lda,
                                           const float* __restrict__ Bt, int ldk,
                                           int n0, int k0,
                                           const int* __restrict__ rowidx,
                                           float* As, float* Bs) {
    int t = threadIdx.x;
#pragma unroll
    for (int i = 0; i < 4; ++i) {
        int ci = t + i*NT;
        int row = ci >> 3, seg = ci & 7;
        cp16(smem_u32(As + row*ASTR + seg*4),
             A + (size_t)rowidx[row]*lda + k0 + seg*4);
    }
#pragma unroll
    for (int i = 0; i < 4; ++i) {
        int ci = t + i*NT;
        int row = ci >> 3, seg = ci & 7;
        cp16(smem_u32(Bs + row*ASTR + seg*4),
             Bt + (size_t)(n0+row)*ldk + k0 + seg*4);
    }
}

// ---------------- mma mainloop: 3-stage pipeline, ldmatrix for A and B ----------------
__device__ __forceinline__ void mma_mainloop(const float* __restrict__ A, int lda,
                                             const float* __restrict__ Bt, int ldk,
                                             int K, int n0,
                                             const int* __restrict__ rowidx,
                                             float* smem, float acc[4][4][4]) {
    int t = threadIdx.x;
    int wid = t >> 5, lane = t & 31;
    int wm = wid & 1, wn = wid >> 1;

    // ldmatrix lane address patterns (byte offsets within stage)
    int l8 = lane & 7, sel_k = (lane >> 3) & 1, sel_n = (lane >> 4) & 1;
    uint32_t a_off[4];
#pragma unroll
    for (int mt = 0; mt < 4; ++mt) {
        int row = wm*64 + mt*16 + sel_n*8 + l8;           // (lane>>3)&1 selects row+8? see note
        a_off[mt] = (uint32_t)((row*ASTR) * 4);
    }
    // A x4: matrices = (rows r..r+7, k0..3), (rows r..r+7? ) -- keep R5-proven pattern:
    // lanes 0-7: rows r..r+7 k seg0 ; lanes 8-15: rows r+8..r+15 k seg0 ;
    // lanes 16-23: rows r..r+7 k seg1 ; lanes 24-31: rows r+8..r+15 k seg1
    {
        int lhi = (lane >> 3) & 1, lk = lane >> 4;
#pragma unroll
        for (int mt = 0; mt < 4; ++mt) {
            int row = wm*64 + mt*16 + lhi*8 + l8;
            a_off[mt] = (uint32_t)((row*ASTR + lk*4) * 4);
        }
    }
    // B x4: matrices = (n..n+7, k seg0), (n..n+7, k seg1), (n+8..n+15, seg0), (n+8..n+15, seg1)
    uint32_t b_off[2];
#pragma unroll
    for (int p = 0; p < 2; ++p) {
        int row = wn*32 + p*16 + sel_n*8 + l8;
        b_off[p] = (uint32_t)(ABUF*4 + (row*ASTR + sel_k*4) * 4);
    }

    int nch = K / BK;
    load_chunk(A, lda, Bt, ldk, n0, 0,  rowidx, smem,         smem + ABUF);
    cp_commit();
    load_chunk(A, lda, Bt, ldk, n0, BK, rowidx, smem + STAGE, smem + STAGE + ABUF);
    cp_commit();

    for (int c = 0; c < nch; ++c) {
        cp_wait1();
        __syncthreads();
        uint32_t st_base = smem_u32(smem + (c % NSTAGE)*STAGE);
#pragma unroll
        for (int ks = 0; ks < 4; ++ks) {
            uint32_t kb = (uint32_t)(ks * 32);    // 8 floats = 32 bytes
            uint32_t af[4][4], bf[4][2];
#pragma unroll
            for (int mt = 0; mt < 4; ++mt)
                ldsm_x4(af[mt][0], af[mt][1], af[mt][2], af[mt][3],
                        st_base + a_off[mt] + kb);
#pragma unroll
            for (int p = 0; p < 2; ++p)
                ldsm_x4(bf[2*p][0], bf[2*p][1], bf[2*p+1][0], bf[2*p+1][1],
                        st_base + b_off[p] + kb);
#pragma unroll
            for (int mt = 0; mt < 4; ++mt)
#pragma unroll
                for (int nt = 0; nt < 4; ++nt)
                    mma_tf32(acc[mt][nt][0], acc[mt][nt][1],
                             acc[mt][nt][2], acc[mt][nt][3],
                             af[mt][0], af[mt][1], af[mt][2], af[mt][3],
                             bf[nt][0], bf[nt][1]);
        }
        if (c + 2 < nch) {
            int st = (c + 2) % NSTAGE;
            load_chunk(A, lda, Bt, ldk, n0, (c+2)*BK, rowidx,
                       smem + st*STAGE, smem + st*STAGE + ABUF);
        }
        cp_commit();   // uniform group count (empty at tail)
    }
}

__device__ __forceinline__ float gelu_exact(float v) {
    return 0.5f * v * (1.0f + erff(v * 0.70710678118654752f));
}

// ---------------- main MLP GEMM1: h = round(gelu(xnorm @ W1 + b1)) ----------------
__global__ void __launch_bounds__(NT, 2) k_gemm1_main(const float* __restrict__ b1) {
    extern __shared__ float smem[];
    __shared__ int s_row[BM];
    int t = threadIdx.x;
    int m0 = blockIdx.y * BM, n0 = blockIdx.x * BN;
    if (t < BM) s_row[t] = m0 + t;
    __syncthreads();
    float acc[4][4][4] = {};
    mma_mainloop(g_xnorm, DIM, g_W1t, DIM, DIM, n0, s_row, smem, acc);
    int wid = t >> 5, lane = t & 31;
    int wm = wid & 1, wn = wid >> 1, qid = lane >> 2, qtr = lane & 3;
#pragma unroll
    for (int mt = 0; mt < 4; ++mt) {
        int r0 = m0 + wm*64 + mt*16 + qid;
#pragma unroll
        for (int nt = 0; nt < 4; ++nt) {
            int col = n0 + wn*32 + nt*8 + qtr*2;
            float bx = b1[col], by = b1[col+1];
            *(float2*)(g_h + (size_t)r0*HID + col) =
                make_float2(round_tf32f(gelu_exact(acc[mt][nt][0]+bx)),
                            round_tf32f(gelu_exact(acc[mt][nt][1]+by)));
            *(float2*)(g_h + (size_t)(r0+8)*HID + col) =
                make_float2(round_tf32f(gelu_exact(acc[mt][nt][2]+bx)),
                            round_tf32f(gelu_exact(acc[mt][nt][3]+by)));
        }
    }
}

// ---------------- fused mid kernel: gemm2_main tiles + gemm1_adapt tiles ----------------
__global__ void __launch_bounds__(NT, 2) k_mid(const float* __restrict__ b2,
                                               const float* __restrict__ a1b) {
    extern __shared__ float smem[];
    __shared__ int s_row[BM];
    int t = threadIdx.x;
    int bid = blockIdx.x;
    int wid = t >> 5, lane = t & 31;
    int wm = wid & 1, wn = wid >> 1, qid = lane >> 2, qtr = lane & 3;

    if (bid < MID_MAIN_BLKS) {
        // ---- main = g_h @ W2 + b2 ----
        int m0 = (bid / 6) * BM, n0 = (bid % 6) * BN;
        if (t < BM) s_row[t] = m0 + t;
        __syncthreads();
        float acc[4][4][4] = {};
        mma_mainloop(g_h, HID, g_W2t, HID, HID, n0, s_row, smem, acc);
#pragma unroll
        for (int mt = 0; mt < 4; ++mt) {
            int r0 = m0 + wm*64 + mt*16 + qid;
#pragma unroll
            for (int nt = 0; nt < 4; ++nt) {
                int col = n0 + wn*32 + nt*8 + qtr*2;
                float bx = b2[col], by = b2[col+1];
                *(float2*)(g_main + (size_t)r0*DIM + col) =
                    make_float2(acc[mt][nt][0]+bx, acc[mt][nt][1]+by);
                *(float2*)(g_main + (size_t)(r0+8)*DIM + col) =
                    make_float2(acc[mt][nt][2]+bx, acc[mt][nt][3]+by);
            }
        }
    } else {
        // ---- hl = round(relu(xnorm[perm] @ A1[lvl] + a1b[lvl])) ----
        int b2i = bid - MID_MAIN_BLKS;
        int tile = b2i / 12;
        if (tile >= g_ntiles) return;
        int n0 = (b2i % 12) * BN;
        int lvl = g_sched_lvl[tile], start = g_sched_start[tile], rows = g_sched_rows[tile];
        if (t < BM) s_row[t] = g_rowperm[start + min(t, rows-1)];
        __syncthreads();
        float acc[4][4][4] = {};
        mma_mainloop(g_xnorm, DIM, g_A1t + (size_t)lvl*DIM*HID2, DIM, DIM, n0,
                     s_row, smem, acc);
        const float* bb = a1b + (size_t)lvl*HID2;
#pragma unroll
        for (int mt = 0; mt < 4; ++mt) {
            int ml = wm*64 + mt*16 + qid;
#pragma unroll
            for (int nt = 0; nt < 4; ++nt) {
                int col = n0 + wn*32 + nt*8 + qtr*2;
                float bx = bb[col], by = bb[col+1];
                if (ml < rows)
                    *(float2*)(g_hl + (size_t)(start+ml)*HID2 + col) =
                        make_float2(round_tf32f(fmaxf(acc[mt][nt][0]+bx, 0.f)),
                                    round_tf32f(fmaxf(acc[mt][nt][1]+by, 0.f)));
                if (ml+8 < rows)
                    *(float2*)(g_hl + (size_t)(start+ml+8)*HID2 + col) =
                        make_float2(round_tf32f(fmaxf(acc[mt][nt][2]+bx, 0.f)),
                                    round_tf32f(fmaxf(acc[mt][nt][3]+by, 0.f)));
            }
        }
    }
}

// ---------------- adapter GEMM2 + final combine ----------------
__global__ void __launch_bounds__(NT, 2) k_gemm2_adapt(const float* __restrict__ a2b,
                                                       float* __restrict__ out) {
    if ((int)blockIdx.y >= g_ntiles) return;
    extern __shared__ float smem[];
    __shared__ int s_row[BM];
    int t = threadIdx.x;
    int tile = blockIdx.y;
    int lvl = g_sched_lvl[tile], start = g_sched_start[tile], rows = g_sched_rows[tile];
    int n0 = blockIdx.x * BN;
    if (t < BM) s_row[t] = min(start + t, MROWS-1);   // g_hl rows are compacted
    __syncthreads();
    float acc[4][4][4] = {};
    mma_mainloop(g_hl, HID2, g_A2t + (size_t)lvl*HID2*DIM, HID2, HID2, n0, s_row, smem, acc);
    int wid = t >> 5, lane = t & 31;
    int wm = wid & 1, wn = wid >> 1, qid = lane >> 2, qtr = lane & 3;
    const float* bb = a2b + (size_t)lvl*DIM;
#pragma unroll
    for (int mt = 0; mt < 4; ++mt) {
        int ml = wm*64 + mt*16 + qid;
#pragma unroll
        for (int nt = 0; nt < 4; ++nt) {
            int col = n0 + wn*32 + nt*8 + qtr*2;
            float bx = bb[col], by = bb[col+1];
            if (ml < rows) {
                int r = g_rowperm[start + ml];
                float mix = g_mix[r & (SEQ-1)];
                const float* mp = g_main + (size_t)r*DIM + col;
                *(float2*)(out + (size_t)r*DIM + col) =
                    make_float2(mp[0]*(1.f-mix) + (acc[mt][nt][0]+bx)*mix,
                                mp[1]*(1.f-mix) + (acc[mt][nt][1]+by)*mix);
            }
            if (ml+8 < rows) {
                int r = g_rowperm[start + ml + 8];
                float mix = g_mix[r & (SEQ-1)];
                const float* mp = g_main + (size_t)r*DIM + col;
                *(float2*)(out + (size_t)r*DIM + col) =
                    make_float2(mp[0]*(1.f-mix) + (acc[mt][nt][2]+bx)*mix,
                                mp[1]*(1.f-mix) + (acc[mt][nt][3]+by)*mix);
            }
        }
    }
}

// ---------------- launch ----------------
extern "C" void kernel_launch(void* const* d_in, const int* in_sizes, int n_in,
                              void* d_out, int out_size) {
    const float* x      = (const float*)d_in[0];
    const int*   levels = (const int*)  d_in[1];
    const float* gamma  = (const float*)d_in[2];
    const float* beta   = (const float*)d_in[3];
    const float* W1     = (const float*)d_in[4];
    const float* b1     = (const float*)d_in[5];
    const float* W2     = (const float*)d_in[6];
    const float* b2     = (const float*)d_in[7];
    const float* A1     = (const float*)d_in[8];
    const float* a1b    = (const float*)d_in[9];
    const float* A2     = (const float*)d_in[10];
    const float* a2b    = (const float*)d_in[11];
    const float* lmw    = (const float*)d_in[12];
    float* out = (float*)d_out;

    cudaFuncSetAttribute(k_gemm1_main,  cudaFuncAttributeMaxDynamicSharedMemorySize, SMEM_BYTES);
    cudaFuncSetAttribute(k_mid,         cudaFuncAttributeMaxDynamicSharedMemorySize, SMEM_BYTES);
    cudaFuncSetAttribute(k_gemm2_adapt, cudaFuncAttributeMaxDynamicSharedMemorySize, SMEM_BYTES);

    float *w1t, *w2t, *a1t, *a2t;
    cudaGetSymbolAddress((void**)&w1t, g_W1t);
    cudaGetSymbolAddress((void**)&w2t, g_W2t);
    cudaGetSymbolAddress((void**)&a1t, g_A1t);
    cudaGetSymbolAddress((void**)&a2t, g_A2t);

    trans_round<<<dim3(HID/32,  DIM/32, 1),    256>>>(W1, w1t, DIM,  HID);
    trans_round<<<dim3(DIM/32,  HID/32, 1),    256>>>(W2, w2t, HID,  DIM);
    trans_round<<<dim3(HID2/32, DIM/32, NLEV), 256>>>(A1, a1t, DIM,  HID2);
    trans_round<<<dim3(DIM/32,  HID2/32,NLEV), 256>>>(A2, a2t, HID2, DIM);

    prep_kernel<<<1, NT>>>(levels, lmw);
    ln_kernel<<<MROWS, 256>>>(x, gamma, beta);
    k_gemm1_main <<<dim3(HID/BN, MROWS/BM), NT, SMEM_BYTES>>>(b1);
    k_mid        <<<MID_BLKS, NT, SMEM_BYTES>>>(b2, a1b);
    k_gemm2_adapt<<<dim3(DIM/BN, MAX_TILES), NT, SMEM_BYTES>>>(a2b, out);
}